// round 11
// baseline (speedup 1.0000x reference)
#include <cuda_runtime.h>
#include <cuda_bf16.h>
#include <math_constants.h>
#include <cstdint>

#define NHEAD 16
#define HDIM  64
#define SEQ   2048
#define BATCH 2
#define CDIM  1024
#define MROWS (BATCH*SEQ)   // 4096
#define BHN   (BATCH*NHEAD) // 32

// ---------------- scratch ----------------
__device__ float g_qkv[(size_t)MROWS * 3 * CDIM];
__device__ float g_cos[SEQ*HDIM];
__device__ float g_sin[SEQ*HDIM];
__device__ __align__(256) __nv_bfloat16 g_Qh[(size_t)BHN*SEQ*HDIM];
__device__ __align__(256) __nv_bfloat16 g_Ql[(size_t)BHN*SEQ*HDIM];
__device__ __align__(256) __nv_bfloat16 g_Kh[(size_t)BHN*SEQ*HDIM];
__device__ __align__(256) __nv_bfloat16 g_Kl[(size_t)BHN*SEQ*HDIM];
__device__ __align__(256) __nv_bfloat16 g_Vh[(size_t)BHN*SEQ*HDIM];
__device__ __align__(256) __nv_bfloat16 g_Vl[(size_t)BHN*SEQ*HDIM];
__device__ __align__(256) __nv_bfloat16 g_Ahi[(size_t)MROWS*CDIM];
__device__ __align__(256) __nv_bfloat16 g_Alo[(size_t)MROWS*CDIM];
__device__ __align__(256) __nv_bfloat16 g_Bhi[(size_t)3*CDIM*CDIM];
__device__ __align__(256) __nv_bfloat16 g_Blo[(size_t)3*CDIM*CDIM];

static __device__ __forceinline__ uint32_t smem_u32(const void* p) {
  uint32_t a;
  asm("{ .reg .u64 t; cvta.to.shared.u64 t, %1; cvt.u32.u64 %0, t; }" : "=r"(a) : "l"(p));
  return a;
}
static __device__ __forceinline__ uint32_t packbf2(float even, float odd) {
  uint32_t r;
  asm("cvt.rn.bf16x2.f32 %0, %1, %2;" : "=r"(r) : "f"(odd), "f"(even));
  return r;
}
static __device__ __forceinline__ uint32_t packresid(uint32_t hi, float even, float odd) {
  float e = __uint_as_float(hi << 16);
  float o = __uint_as_float(hi & 0xFFFF0000u);
  return packbf2(even - e, odd - o);
}

// ---------------- RoPE cos/sin cache ----------------
__global__ void rope_cache_kernel() {
  int idx = blockIdx.x*blockDim.x + threadIdx.x;
  if (idx >= SEQ*HDIM) return;
  int t = idx >> 6;
  int d = idx & 63;
  int j = d & 31;
  float inv = powf(10000.0f, -(float)j / 32.0f);
  float ang = (float)t * inv;
  float s, c;
  sincosf(ang, &s, &c);
  g_cos[idx] = c;
  g_sin[idx] = s;
}

// ---------------- fp32 -> bf16 hi/lo split ----------------
__global__ void conv_split_kernel(const float* __restrict__ src,
                                  __nv_bfloat16* __restrict__ hi,
                                  __nv_bfloat16* __restrict__ lo, int n) {
  int i = (blockIdx.x*blockDim.x + threadIdx.x) * 4;
  if (i >= n) return;
  float4 v = *(const float4*)(src + i);
  __nv_bfloat16 h0 = __float2bfloat16(v.x);
  __nv_bfloat16 h1 = __float2bfloat16(v.y);
  __nv_bfloat16 h2 = __float2bfloat16(v.z);
  __nv_bfloat16 h3 = __float2bfloat16(v.w);
  __nv_bfloat16 l0 = __float2bfloat16(v.x - __bfloat162float(h0));
  __nv_bfloat16 l1 = __float2bfloat16(v.y - __bfloat162float(h1));
  __nv_bfloat16 l2 = __float2bfloat16(v.z - __bfloat162float(h2));
  __nv_bfloat16 l3 = __float2bfloat16(v.w - __bfloat162float(h3));
  __nv_bfloat162* hp = (__nv_bfloat162*)(hi + i);
  __nv_bfloat162* lp = (__nv_bfloat162*)(lo + i);
  hp[0] = __nv_bfloat162(h0, h1); hp[1] = __nv_bfloat162(h2, h3);
  lp[0] = __nv_bfloat162(l0, l1); lp[1] = __nv_bfloat162(l2, l3);
}

// ================= mma macros =================
#define LDSM4(R,ADDR) \
  asm volatile("ldmatrix.sync.aligned.m8n8.x4.shared.b16 {%0,%1,%2,%3}, [%4];" \
    : "=r"((R)[0]),"=r"((R)[1]),"=r"((R)[2]),"=r"((R)[3]) : "r"(ADDR))
#define LDSM4T(R,ADDR) \
  asm volatile("ldmatrix.sync.aligned.m8n8.x4.trans.shared.b16 {%0,%1,%2,%3}, [%4];" \
    : "=r"((R)[0]),"=r"((R)[1]),"=r"((R)[2]),"=r"((R)[3]) : "r"(ADDR))
#define MMA16816(D,A,B) \
  asm volatile("mma.sync.aligned.m16n8k16.row.col.f32.bf16.bf16.f32 " \
    "{%0,%1,%2,%3}, {%4,%5,%6,%7}, {%8,%9}, {%0,%1,%2,%3};" \
    : "+f"((D)[0]),"+f"((D)[1]),"+f"((D)[2]),"+f"((D)[3]) \
    : "r"((A)[0]),"r"((A)[1]),"r"((A)[2]),"r"((A)[3]), "r"((B)[0]),"r"((B)[1]))
#define CPASYNC16(DST,SRC) \
  asm volatile("cp.async.cg.shared.global [%0], [%1], 16;" :: "r"(DST), "l"(SRC) : "memory")

// ================= 3xBF16 mma.sync GEMM: C[M,N] = A[M,K] * B[N,K]^T =================
// Single __syncthreads per ktile: wait -> sync -> issue next stage -> compute.
#define GP 40
#define COMP_BYTES (128*GP*2)
#define STAGE_BYTES (4*COMP_BYTES)
#define GSM_TOTAL (2*STAGE_BYTES)

__global__ __launch_bounds__(256, 2)
void gemm_bf16x3(const __nv_bfloat16* __restrict__ Ahi, const __nv_bfloat16* __restrict__ Alo,
                 const __nv_bfloat16* __restrict__ Bhi, const __nv_bfloat16* __restrict__ Blo,
                 float* __restrict__ C, int M, int N, int K) {
  extern __shared__ char sm[];
  const uint32_t sb = smem_u32(sm);
  const int tid = threadIdx.x, warp = tid >> 5, lane = tid & 31;
  const int m0 = blockIdx.y * 128, n0 = blockIdx.x * 128;
  const int warp_m = (warp >> 1) * 32, warp_n = (warp & 1) * 64;

  float acc[2][8][4];
#pragma unroll
  for (int f = 0; f < 2; f++)
#pragma unroll
    for (int t = 0; t < 8; t++)
#pragma unroll
      for (int j = 0; j < 4; j++) acc[f][t][j] = 0.f;

  const __nv_bfloat16* srcs[4] = {Ahi, Alo, Bhi, Blo};
  auto load_stage = [&](int stage, int k0) {
#pragma unroll
    for (int i = 0; i < 8; i++) {
      int t = tid + i * 256;
      int comp = t >> 9, row = (t >> 2) & 127, ch = t & 3;
      const __nv_bfloat16* src = srcs[comp] +
        (size_t)((comp < 2 ? m0 : n0) + row) * K + k0 + ch * 8;
      uint32_t dst = sb + stage * STAGE_BYTES + comp * COMP_BYTES + row * (GP*2) + ch * 16;
      CPASYNC16(dst, src);
    }
    asm volatile("cp.async.commit_group;" ::: "memory");
  };

  const int NIT = K / 32;
  load_stage(0, 0);
  for (int kt = 0; kt < NIT; kt++) {
    asm volatile("cp.async.wait_group 0;" ::: "memory");
    __syncthreads();
    if (kt + 1 < NIT) load_stage((kt + 1) & 1, (kt + 1) * 32);

    const uint32_t base = sb + (kt & 1) * STAGE_BYTES;
#pragma unroll
    for (int ks = 0; ks < 2; ks++) {
      uint32_t ah[2][4], al[2][4];
      {
        int arow = (lane & 7) + ((lane >> 3) & 1) * 8;
        int akof = ks * 16 + ((lane >> 4) & 1) * 8;
#pragma unroll
        for (int f = 0; f < 2; f++) {
          uint32_t ao = base + (warp_m + f * 16 + arow) * (GP*2) + akof * 2;
          LDSM4(ah[f], ao);
          LDSM4(al[f], ao + COMP_BYTES);
        }
      }
      int brow = (lane & 7) + ((lane >> 4) & 1) * 8;
      int bkof = ks * 16 + ((lane >> 3) & 1) * 8;
#pragma unroll
      for (int p = 0; p < 4; p++) {
        uint32_t bo = base + 2 * COMP_BYTES + (warp_n + p * 16 + brow) * (GP*2) + bkof * 2;
        uint32_t bh[4], bl[4];
        LDSM4(bh, bo);
        LDSM4(bl, bo + COMP_BYTES);
#pragma unroll
        for (int half = 0; half < 2; half++) {
          int t = p * 2 + half;
          uint32_t* bhp = bh + half * 2;
          uint32_t* blp = bl + half * 2;
#pragma unroll
          for (int f = 0; f < 2; f++) {
            MMA16816(acc[f][t], ah[f], bhp);
            MMA16816(acc[f][t], ah[f], blp);
            MMA16816(acc[f][t], al[f], bhp);
          }
        }
      }
    }
  }
  const int g = lane >> 2, tig = lane & 3;
#pragma unroll
  for (int f = 0; f < 2; f++) {
#pragma unroll
    for (int t = 0; t < 8; t++) {
      int row = m0 + warp_m + f * 16 + g;
      int col = n0 + warp_n + t * 8 + tig * 2;
      *(float2*)&C[(size_t)row * N + col]       = make_float2(acc[f][t][0], acc[f][t][1]);
      *(float2*)&C[(size_t)(row + 8) * N + col] = make_float2(acc[f][t][2], acc[f][t][3]);
    }
  }
}

// ---------------- RoPE apply + split to bf16 hi/lo, head-major ----------------
__global__ void rope_apply_kernel() {
  int p = blockIdx.x*blockDim.x + threadIdx.x;
  if (p >= MROWS*1536) return;
  int m   = p / 1536;
  int col = (p % 1536) * 2;
  int b = m >> 11;
  int t = m & 2047;
  int sec = col >> 10;
  int cc  = col & 1023;
  int h = cc >> 6;
  int d = cc & 63;
  float2 v = *(const float2*)&g_qkv[(size_t)m*3072 + col];
  float r0, r1;
  if (sec < 2) {
    float c0 = g_cos[t*64 + d],     s0 = g_sin[t*64 + d];
    float c1 = g_cos[t*64 + d + 1], s1 = g_sin[t*64 + d + 1];
    r0 = v.x*c0 - v.y*s0;
    r1 = v.y*c1 + v.x*s1;
  } else { r0 = v.x; r1 = v.y; }
  if (sec == 0) { r0 *= 0.125f; r1 *= 0.125f; }
  __nv_bfloat16 h0 = __float2bfloat16(r0), h1 = __float2bfloat16(r1);
  __nv_bfloat16 l0 = __float2bfloat16(r0 - __bfloat162float(h0));
  __nv_bfloat16 l1 = __float2bfloat16(r1 - __bfloat162float(h1));
  __nv_bfloat16 *dh = (sec == 0) ? g_Qh : (sec == 1) ? g_Kh : g_Vh;
  __nv_bfloat16 *dl = (sec == 0) ? g_Ql : (sec == 1) ? g_Kl : g_Vl;
  size_t o = ((size_t)((b*NHEAD + h)*SEQ + t))*HDIM + d;
  *(__nv_bfloat162*)&dh[o] = __nv_bfloat162(h0, h1);
  *(__nv_bfloat162*)&dl[o] = __nv_bfloat162(l0, l1);
}

// ================= tensor-core flash attention, 64-key tiles, 2 CTAs/SM =================
// 256 thr / 8 warps; warp w owns q rows [q0+16w, +16). Double-buffered 64-key KV tiles.
// smem: Qh,Ql areas 128x144B; then 2 bufs x {Kh,Kl,Vh,Vl} areas 64x144B.
#define AQ_P    144
#define AQ_AREA (128*AQ_P)         // 18432
#define KV_AREA (64*AQ_P)          // 9216
#define KV_BASE (2*AQ_AREA)        // 36864
#define ATT2_SMEM (KV_BASE + 8*KV_AREA)  // 110592
#define NKT (SEQ/64)               // 32

__global__ __launch_bounds__(256, 2)
void flash_attn_tc() {
  extern __shared__ char smb[];
  const uint32_t sb = smem_u32(smb);
  const int tid = threadIdx.x, w = tid >> 5, lane = tid & 31;
  const int g = lane >> 2, tig = lane & 3;
  const int q0 = blockIdx.x * 128;
  const int bh = blockIdx.y;
  const size_t base = (size_t)bh * SEQ * HDIM;
  const __nv_bfloat16* kvsrc[4] = { g_Kh + base, g_Kl + base, g_Vh + base, g_Vl + base };

  auto stage_kv = [&](int kt, int buf) {
#pragma unroll
    for (int i = 0; i < 8; i++) {
      int t = tid + i * 256;
      int comp = t >> 9, r = (t >> 3) & 63, ch = t & 7;
      const void* src = kvsrc[comp] + (size_t)(kt * 64 + r) * 64 + ch * 8;
      uint32_t dst = sb + KV_BASE + (buf * 4 + comp) * KV_AREA + r * AQ_P + ch * 16;
      CPASYNC16(dst, src);
    }
    asm volatile("cp.async.commit_group;" ::: "memory");
  };

  // stage Q (group 0) + KV tile 0 (group 1)
  {
    const __nv_bfloat16* qs[2] = { g_Qh + base, g_Ql + base };
#pragma unroll
    for (int i = 0; i < 8; i++) {
      int t = tid + i * 256;
      int comp = t >> 10, r = (t >> 3) & 127, ch = t & 7;
      const void* src = qs[comp] + (size_t)(q0 + r) * 64 + ch * 8;
      uint32_t dst = sb + comp * AQ_AREA + r * AQ_P + ch * 16;
      CPASYNC16(dst, src);
    }
    asm volatile("cp.async.commit_group;" ::: "memory");
  }
  stage_kv(0, 0);
  asm volatile("cp.async.wait_group 1;" ::: "memory");  // Q ready (KV0 may fly)
  __syncthreads();

  // Qhi fragments -> registers; Qlo stays in smem (reloaded per ktile)
  uint32_t qh[4][4];
  uint32_t qro[4];
#pragma unroll
  for (int ks = 0; ks < 4; ks++) {
    qro[ks] = (uint32_t)((w * 16 + (lane & 7) + ((lane >> 3) & 1) * 8) * AQ_P
                       + (ks * 16 + ((lane >> 4) & 1) * 8) * 2);
    LDSM4(qh[ks], sb + qro[ks]);
  }

  float m0 = -CUDART_INF_F, m1 = -CUDART_INF_F, l0 = 0.f, l1 = 0.f;
  float o[8][4];
#pragma unroll
  for (int t = 0; t < 8; t++)
#pragma unroll
    for (int j = 0; j < 4; j++) o[t][j] = 0.f;

  for (int kt = 0; kt < NKT; kt++) {
    asm volatile("cp.async.wait_group 0;" ::: "memory");
    __syncthreads();
    if (kt + 1 < NKT) stage_kv(kt + 1, (kt + 1) & 1);
    const uint32_t kb = sb + KV_BASE + (kt & 1) * 4 * KV_AREA;

    // ---- S = Q @ K^T (3 terms), 64 keys ----
    float s[8][4];
#pragma unroll
    for (int nt = 0; nt < 8; nt++)
#pragma unroll
      for (int j = 0; j < 4; j++) s[nt][j] = 0.f;
#pragma unroll
    for (int ks = 0; ks < 4; ks++) {
      uint32_t qlf[4];
      LDSM4(qlf, sb + AQ_AREA + qro[ks]);
#pragma unroll
      for (int jj = 0; jj < 4; jj++) {
        uint32_t ro = (uint32_t)((jj * 16 + (lane & 7) + ((lane >> 4) & 1) * 8) * AQ_P
                               + (ks * 16 + ((lane >> 3) & 1) * 8) * 2);
        uint32_t bh4[4], bl4[4];
        LDSM4(bh4, kb + ro);
        LDSM4(bl4, kb + KV_AREA + ro);
        MMA16816(s[2*jj],   qh[ks], bh4);
        MMA16816(s[2*jj],   qh[ks], bl4);
        MMA16816(s[2*jj],   qlf,    bh4);
        MMA16816(s[2*jj+1], qh[ks], bh4 + 2);
        MMA16816(s[2*jj+1], qh[ks], bl4 + 2);
        MMA16816(s[2*jj+1], qlf,    bh4 + 2);
      }
    }

    // ---- online softmax (rows g and g+8) ----
    float mx0 = s[0][0], mx1 = s[0][2];
#pragma unroll
    for (int nt = 0; nt < 8; nt++) {
      mx0 = fmaxf(mx0, fmaxf(s[nt][0], s[nt][1]));
      mx1 = fmaxf(mx1, fmaxf(s[nt][2], s[nt][3]));
    }
    mx0 = fmaxf(mx0, __shfl_xor_sync(0xffffffffu, mx0, 1));
    mx0 = fmaxf(mx0, __shfl_xor_sync(0xffffffffu, mx0, 2));
    mx1 = fmaxf(mx1, __shfl_xor_sync(0xffffffffu, mx1, 1));
    mx1 = fmaxf(mx1, __shfl_xor_sync(0xffffffffu, mx1, 2));
    float mn0 = fmaxf(m0, mx0), mn1 = fmaxf(m1, mx1);
    float a0 = __expf(m0 - mn0), a1 = __expf(m1 - mn1);
    float rs0 = 0.f, rs1 = 0.f;
#pragma unroll
    for (int nt = 0; nt < 8; nt++) {
      s[nt][0] = __expf(s[nt][0] - mn0); rs0 += s[nt][0];
      s[nt][1] = __expf(s[nt][1] - mn0); rs0 += s[nt][1];
      s[nt][2] = __expf(s[nt][2] - mn1); rs1 += s[nt][2];
      s[nt][3] = __expf(s[nt][3] - mn1); rs1 += s[nt][3];
    }
    rs0 += __shfl_xor_sync(0xffffffffu, rs0, 1);
    rs0 += __shfl_xor_sync(0xffffffffu, rs0, 2);
    rs1 += __shfl_xor_sync(0xffffffffu, rs1, 1);
    rs1 += __shfl_xor_sync(0xffffffffu, rs1, 2);
    l0 = l0 * a0 + rs0; l1 = l1 * a1 + rs1;
    m0 = mn0; m1 = mn1;
#pragma unroll
    for (int t = 0; t < 8; t++) {
      o[t][0] *= a0; o[t][1] *= a0; o[t][2] *= a1; o[t][3] *= a1;
    }

    // ---- O += P @ V (3 terms); P from registers (C->A fragment identity) ----
#pragma unroll
    for (int J = 0; J < 4; J++) {
      uint32_t pah[4], pal[4];
      pah[0] = packbf2(s[2*J][0],   s[2*J][1]);
      pah[1] = packbf2(s[2*J][2],   s[2*J][3]);
      pah[2] = packbf2(s[2*J+1][0], s[2*J+1][1]);
      pah[3] = packbf2(s[2*J+1][2], s[2*J+1][3]);
      pal[0] = packresid(pah[0], s[2*J][0],   s[2*J][1]);
      pal[1] = packresid(pah[1], s[2*J][2],   s[2*J][3]);
      pal[2] = packresid(pah[2], s[2*J+1][0], s[2*J+1][1]);
      pal[3] = packresid(pah[3], s[2*J+1][2], s[2*J+1][3]);
#pragma unroll
      for (int tt = 0; tt < 4; tt++) {
        uint32_t ro = (uint32_t)((J * 16 + (lane & 7) + ((lane >> 3) & 1) * 8) * AQ_P
                               + (tt * 16 + ((lane >> 4) & 1) * 8) * 2);
        uint32_t vh4[4], vl4[4];
        LDSM4T(vh4, kb + 2 * KV_AREA + ro);
        LDSM4T(vl4, kb + 3 * KV_AREA + ro);
        MMA16816(o[2*tt],   pah, vh4);
        MMA16816(o[2*tt],   pah, vl4);
        MMA16816(o[2*tt],   pal, vh4);
        MMA16816(o[2*tt+1], pah, vh4 + 2);
        MMA16816(o[2*tt+1], pah, vl4 + 2);
        MMA16816(o[2*tt+1], pal, vh4 + 2);
      }
    }
  }

  // ---- epilogue: normalize + split write into gemm2 A staging ----
  const float i0 = 1.f / l0, i1 = 1.f / l1;
  const int b = bh >> 4, h = bh & 15;
  const int r0 = q0 + w * 16 + g, r1 = r0 + 8;
  const size_t ro0 = (size_t)(b * SEQ + r0) * CDIM + h * 64;
  const size_t ro1 = (size_t)(b * SEQ + r1) * CDIM + h * 64;
#pragma unroll
  for (int t = 0; t < 8; t++) {
    int col = t * 8 + tig * 2;
    float f0 = o[t][0] * i0, f1 = o[t][1] * i0;
    float f2 = o[t][2] * i1, f3 = o[t][3] * i1;
    uint32_t h0 = packbf2(f0, f1), h1 = packbf2(f2, f3);
    *(uint32_t*)&g_Ahi[ro0 + col] = h0;
    *(uint32_t*)&g_Alo[ro0 + col] = packresid(h0, f0, f1);
    *(uint32_t*)&g_Ahi[ro1 + col] = h1;
    *(uint32_t*)&g_Alo[ro1 + col] = packresid(h1, f2, f3);
  }
}

// ---------------- launch ----------------
extern "C" void kernel_launch(void* const* d_in, const int* in_sizes, int n_in,
                              void* d_out, int out_size) {
  const float* x    = (const float*)d_in[0];
  const float* Wqkv = (const float*)d_in[1];
  const float* Wout = (const float*)d_in[2];
  float* out = (float*)d_out;

  float *qkv = nullptr;
  __nv_bfloat16 *Ahi=nullptr,*Alo=nullptr,*Bhi=nullptr,*Blo=nullptr;
  cudaGetSymbolAddress((void**)&qkv, g_qkv);
  cudaGetSymbolAddress((void**)&Ahi, g_Ahi);
  cudaGetSymbolAddress((void**)&Alo, g_Alo);
  cudaGetSymbolAddress((void**)&Bhi, g_Bhi);
  cudaGetSymbolAddress((void**)&Blo, g_Blo);

  cudaFuncSetAttribute(gemm_bf16x3,
                       cudaFuncAttributeMaxDynamicSharedMemorySize, GSM_TOTAL);
  cudaFuncSetAttribute(flash_attn_tc,
                       cudaFuncAttributeMaxDynamicSharedMemorySize, ATT2_SMEM);

  rope_cache_kernel<<<(SEQ*HDIM + 255)/256, 256>>>();
  conv_split_kernel<<<(MROWS*CDIM/4 + 255)/256, 256>>>(x, Ahi, Alo, MROWS*CDIM);
  conv_split_kernel<<<(3*CDIM*CDIM/4 + 255)/256, 256>>>(Wqkv, Bhi, Blo, 3*CDIM*CDIM);
  gemm_bf16x3<<<dim3(3*CDIM/128, MROWS/128), 256, GSM_TOTAL>>>(Ahi, Alo, Bhi, Blo, qkv,
                                                               MROWS, 3*CDIM, CDIM);
  rope_apply_kernel<<<(MROWS*1536 + 255)/256, 256>>>();
  flash_attn_tc<<<dim3(SEQ/128, BHN), 256, ATT2_SMEM>>>();
  conv_split_kernel<<<(CDIM*CDIM/4 + 255)/256, 256>>>(Wout, Bhi, Blo, CDIM*CDIM);
  gemm_bf16x3<<<dim3(CDIM/128, MROWS/128), 256, GSM_TOTAL>>>(Ahi, Alo, Bhi, Blo, out,
                                                             MROWS, CDIM, CDIM);
}

// round 12
// speedup vs baseline: 1.4589x; 1.4589x over previous
#include <cuda_runtime.h>
#include <cuda_bf16.h>
#include <math_constants.h>
#include <cstdint>

#define NHEAD 16
#define HDIM  64
#define SEQ   2048
#define BATCH 2
#define CDIM  1024
#define MROWS (BATCH*SEQ)   // 4096
#define BHN   (BATCH*NHEAD) // 32

// ---------------- scratch ----------------
__device__ float g_qkv[(size_t)MROWS * 3 * CDIM];
__device__ float g_cos[SEQ*HDIM];
__device__ float g_sin[SEQ*HDIM];
__device__ __align__(256) __nv_bfloat16 g_Qh[(size_t)BHN*SEQ*HDIM];
__device__ __align__(256) __nv_bfloat16 g_Ql[(size_t)BHN*SEQ*HDIM];
__device__ __align__(256) __nv_bfloat16 g_Kh[(size_t)BHN*SEQ*HDIM];
__device__ __align__(256) __nv_bfloat16 g_Kl[(size_t)BHN*SEQ*HDIM];
__device__ __align__(256) __nv_bfloat16 g_Vh[(size_t)BHN*SEQ*HDIM];
__device__ __align__(256) __nv_bfloat16 g_Vl[(size_t)BHN*SEQ*HDIM];
__device__ __align__(256) __nv_bfloat16 g_Ahi[(size_t)MROWS*CDIM];
__device__ __align__(256) __nv_bfloat16 g_Alo[(size_t)MROWS*CDIM];
__device__ __align__(256) __nv_bfloat16 g_Bhi[(size_t)3*CDIM*CDIM];
__device__ __align__(256) __nv_bfloat16 g_Blo[(size_t)3*CDIM*CDIM];

static __device__ __forceinline__ uint32_t smem_u32(const void* p) {
  uint32_t a;
  asm("{ .reg .u64 t; cvta.to.shared.u64 t, %1; cvt.u32.u64 %0, t; }" : "=r"(a) : "l"(p));
  return a;
}
static __device__ __forceinline__ uint32_t packbf2(float even, float odd) {
  uint32_t r;
  asm("cvt.rn.bf16x2.f32 %0, %1, %2;" : "=r"(r) : "f"(odd), "f"(even));
  return r;
}
static __device__ __forceinline__ uint32_t packresid(uint32_t hi, float even, float odd) {
  float e = __uint_as_float(hi << 16);
  float o = __uint_as_float(hi & 0xFFFF0000u);
  return packbf2(even - e, odd - o);
}

// ---------------- RoPE cos/sin cache ----------------
__global__ void rope_cache_kernel() {
  int idx = blockIdx.x*blockDim.x + threadIdx.x;
  if (idx >= SEQ*HDIM) return;
  int t = idx >> 6;
  int d = idx & 63;
  int j = d & 31;
  float inv = powf(10000.0f, -(float)j / 32.0f);
  float ang = (float)t * inv;
  float s, c;
  sincosf(ang, &s, &c);
  g_cos[idx] = c;
  g_sin[idx] = s;
}

// ---------------- fp32 -> bf16 hi/lo split ----------------
__global__ void conv_split_kernel(const float* __restrict__ src,
                                  __nv_bfloat16* __restrict__ hi,
                                  __nv_bfloat16* __restrict__ lo, int n) {
  int i = (blockIdx.x*blockDim.x + threadIdx.x) * 4;
  if (i >= n) return;
  float4 v = *(const float4*)(src + i);
  __nv_bfloat16 h0 = __float2bfloat16(v.x);
  __nv_bfloat16 h1 = __float2bfloat16(v.y);
  __nv_bfloat16 h2 = __float2bfloat16(v.z);
  __nv_bfloat16 h3 = __float2bfloat16(v.w);
  __nv_bfloat16 l0 = __float2bfloat16(v.x - __bfloat162float(h0));
  __nv_bfloat16 l1 = __float2bfloat16(v.y - __bfloat162float(h1));
  __nv_bfloat16 l2 = __float2bfloat16(v.z - __bfloat162float(h2));
  __nv_bfloat16 l3 = __float2bfloat16(v.w - __bfloat162float(h3));
  __nv_bfloat162* hp = (__nv_bfloat162*)(hi + i);
  __nv_bfloat162* lp = (__nv_bfloat162*)(lo + i);
  hp[0] = __nv_bfloat162(h0, h1); hp[1] = __nv_bfloat162(h2, h3);
  lp[0] = __nv_bfloat162(l0, l1); lp[1] = __nv_bfloat162(l2, l3);
}

// ================= mma macros =================
#define LDSM4(R,ADDR) \
  asm volatile("ldmatrix.sync.aligned.m8n8.x4.shared.b16 {%0,%1,%2,%3}, [%4];" \
    : "=r"((R)[0]),"=r"((R)[1]),"=r"((R)[2]),"=r"((R)[3]) : "r"(ADDR))
#define LDSM4T(R,ADDR) \
  asm volatile("ldmatrix.sync.aligned.m8n8.x4.trans.shared.b16 {%0,%1,%2,%3}, [%4];" \
    : "=r"((R)[0]),"=r"((R)[1]),"=r"((R)[2]),"=r"((R)[3]) : "r"(ADDR))
#define MMA16816(D,A,B) \
  asm volatile("mma.sync.aligned.m16n8k16.row.col.f32.bf16.bf16.f32 " \
    "{%0,%1,%2,%3}, {%4,%5,%6,%7}, {%8,%9}, {%0,%1,%2,%3};" \
    : "+f"((D)[0]),"+f"((D)[1]),"+f"((D)[2]),"+f"((D)[3]) \
    : "r"((A)[0]),"r"((A)[1]),"r"((A)[2]),"r"((A)[3]), "r"((B)[0]),"r"((B)[1]))
#define CPASYNC16(DST,SRC) \
  asm volatile("cp.async.cg.shared.global [%0], [%1], 16;" :: "r"(DST), "l"(SRC) : "memory")

// ================= 3xBF16 mma.sync GEMM: C[M,N] = A[M,K] * B[N,K]^T =================
// R8 pipeline structure (issue-next-stage BEFORE wait). Inner loop reordered
// pass-major: all frags loaded first, then hi*hi / hi*lo / lo*hi sweeps so each
// accumulator's updates are 16 MMAs apart (no RAW stalls).
#define GP 40
#define COMP_BYTES (128*GP*2)
#define STAGE_BYTES (4*COMP_BYTES)
#define GSM_TOTAL (2*STAGE_BYTES)

__global__ __launch_bounds__(256, 2)
void gemm_bf16x3(const __nv_bfloat16* __restrict__ Ahi, const __nv_bfloat16* __restrict__ Alo,
                 const __nv_bfloat16* __restrict__ Bhi, const __nv_bfloat16* __restrict__ Blo,
                 float* __restrict__ C, int M, int N, int K) {
  extern __shared__ char sm[];
  const uint32_t sb = smem_u32(sm);
  const int tid = threadIdx.x, warp = tid >> 5, lane = tid & 31;
  const int m0 = blockIdx.y * 128, n0 = blockIdx.x * 128;
  const int warp_m = (warp >> 1) * 32, warp_n = (warp & 1) * 64;

  float acc[2][8][4];
#pragma unroll
  for (int f = 0; f < 2; f++)
#pragma unroll
    for (int t = 0; t < 8; t++)
#pragma unroll
      for (int j = 0; j < 4; j++) acc[f][t][j] = 0.f;

  const __nv_bfloat16* srcs[4] = {Ahi, Alo, Bhi, Blo};
  auto load_stage = [&](int stage, int k0) {
#pragma unroll
    for (int i = 0; i < 8; i++) {
      int t = tid + i * 256;
      int comp = t >> 9, row = (t >> 2) & 127, ch = t & 3;
      const __nv_bfloat16* src = srcs[comp] +
        (size_t)((comp < 2 ? m0 : n0) + row) * K + k0 + ch * 8;
      uint32_t dst = sb + stage * STAGE_BYTES + comp * COMP_BYTES + row * (GP*2) + ch * 16;
      CPASYNC16(dst, src);
    }
    asm volatile("cp.async.commit_group;" ::: "memory");
  };

  const int NIT = K / 32;
  load_stage(0, 0);
  for (int kt = 0; kt < NIT; kt++) {
    if (kt + 1 < NIT) {
      load_stage((kt + 1) & 1, (kt + 1) * 32);
      asm volatile("cp.async.wait_group 1;" ::: "memory");
    } else {
      asm volatile("cp.async.wait_group 0;" ::: "memory");
    }
    __syncthreads();
    const uint32_t base = sb + (kt & 1) * STAGE_BYTES;
#pragma unroll
    for (int ks = 0; ks < 2; ks++) {
      // ---- load ALL fragments for this k-step ----
      uint32_t ah[2][4], al[2][4];
      {
        int arow = (lane & 7) + ((lane >> 3) & 1) * 8;
        int akof = ks * 16 + ((lane >> 4) & 1) * 8;
#pragma unroll
        for (int f = 0; f < 2; f++) {
          uint32_t ao = base + (warp_m + f * 16 + arow) * (GP*2) + akof * 2;
          LDSM4(ah[f], ao);
          LDSM4(al[f], ao + COMP_BYTES);
        }
      }
      uint32_t bh[4][4], bl[4][4];
      {
        int brow = (lane & 7) + ((lane >> 4) & 1) * 8;
        int bkof = ks * 16 + ((lane >> 3) & 1) * 8;
#pragma unroll
        for (int p = 0; p < 4; p++) {
          uint32_t bo = base + 2 * COMP_BYTES + (warp_n + p * 16 + brow) * (GP*2) + bkof * 2;
          LDSM4(bh[p], bo);
          LDSM4(bl[p], bo + COMP_BYTES);
        }
      }
      // ---- pass 1: hi*hi ----
#pragma unroll
      for (int p = 0; p < 4; p++)
#pragma unroll
        for (int half = 0; half < 2; half++)
#pragma unroll
          for (int f = 0; f < 2; f++)
            MMA16816(acc[f][p*2+half], ah[f], bh[p] + half*2);
      // ---- pass 2: hi*lo ----
#pragma unroll
      for (int p = 0; p < 4; p++)
#pragma unroll
        for (int half = 0; half < 2; half++)
#pragma unroll
          for (int f = 0; f < 2; f++)
            MMA16816(acc[f][p*2+half], ah[f], bl[p] + half*2);
      // ---- pass 3: lo*hi ----
#pragma unroll
      for (int p = 0; p < 4; p++)
#pragma unroll
        for (int half = 0; half < 2; half++)
#pragma unroll
          for (int f = 0; f < 2; f++)
            MMA16816(acc[f][p*2+half], al[f], bh[p] + half*2);
    }
    __syncthreads();
  }
  const int g = lane >> 2, tig = lane & 3;
#pragma unroll
  for (int f = 0; f < 2; f++) {
#pragma unroll
    for (int t = 0; t < 8; t++) {
      int row = m0 + warp_m + f * 16 + g;
      int col = n0 + warp_n + t * 8 + tig * 2;
      *(float2*)&C[(size_t)row * N + col]       = make_float2(acc[f][t][0], acc[f][t][1]);
      *(float2*)&C[(size_t)(row + 8) * N + col] = make_float2(acc[f][t][2], acc[f][t][3]);
    }
  }
}

// ---------------- RoPE apply + split to bf16 hi/lo, head-major ----------------
__global__ void rope_apply_kernel() {
  int p = blockIdx.x*blockDim.x + threadIdx.x;
  if (p >= MROWS*1536) return;
  int m   = p / 1536;
  int col = (p % 1536) * 2;
  int b = m >> 11;
  int t = m & 2047;
  int sec = col >> 10;
  int cc  = col & 1023;
  int h = cc >> 6;
  int d = cc & 63;
  float2 v = *(const float2*)&g_qkv[(size_t)m*3072 + col];
  float r0, r1;
  if (sec < 2) {
    float c0 = g_cos[t*64 + d],     s0 = g_sin[t*64 + d];
    float c1 = g_cos[t*64 + d + 1], s1 = g_sin[t*64 + d + 1];
    r0 = v.x*c0 - v.y*s0;
    r1 = v.y*c1 + v.x*s1;
  } else { r0 = v.x; r1 = v.y; }
  if (sec == 0) { r0 *= 0.125f; r1 *= 0.125f; }
  __nv_bfloat16 h0 = __float2bfloat16(r0), h1 = __float2bfloat16(r1);
  __nv_bfloat16 l0 = __float2bfloat16(r0 - __bfloat162float(h0));
  __nv_bfloat16 l1 = __float2bfloat16(r1 - __bfloat162float(h1));
  __nv_bfloat16 *dh = (sec == 0) ? g_Qh : (sec == 1) ? g_Kh : g_Vh;
  __nv_bfloat16 *dl = (sec == 0) ? g_Ql : (sec == 1) ? g_Kl : g_Vl;
  size_t o = ((size_t)((b*NHEAD + h)*SEQ + t))*HDIM + d;
  *(__nv_bfloat162*)&dh[o] = __nv_bfloat162(h0, h1);
  *(__nv_bfloat162*)&dl[o] = __nv_bfloat162(l0, l1);
}

// ================= tensor-core flash attention (exact R8, proven 304us) =================
#define AP_B   144
#define AREA_B (128*AP_B)          // 18432
#define ATT2_SMEM (10*AREA_B)      // 184320

__global__ __launch_bounds__(256, 1)
void flash_attn_tc() {
  extern __shared__ char smb[];
  const uint32_t sb = smem_u32(smb);
  const int tid = threadIdx.x, w = tid >> 5, lane = tid & 31;
  const int g = lane >> 2, tig = lane & 3;
  const int q0 = blockIdx.x * 128;
  const int bh = blockIdx.y;
  const size_t base = (size_t)bh * SEQ * HDIM;
  const __nv_bfloat16* kvsrc[4] = { g_Kh + base, g_Kl + base, g_Vh + base, g_Vl + base };

  auto stage_kv = [&](int kt, int buf) {
#pragma unroll
    for (int i = 0; i < 16; i++) {
      int t = tid + i * 256;
      int comp = t >> 10, r = (t >> 3) & 127, ch = t & 7;
      const void* src = kvsrc[comp] + (size_t)(kt * 128 + r) * 64 + ch * 8;
      uint32_t dst = sb + (2 + 4 * buf + comp) * AREA_B + r * AP_B + ch * 16;
      CPASYNC16(dst, src);
    }
    asm volatile("cp.async.commit_group;" ::: "memory");
  };

  // stage Q (group 0) + KV tile 0 (group 1)
  {
    const __nv_bfloat16* qs[2] = { g_Qh + base, g_Ql + base };
#pragma unroll
    for (int i = 0; i < 8; i++) {
      int t = tid + i * 256;
      int comp = t >> 10, r = (t >> 3) & 127, ch = t & 7;
      const void* src = qs[comp] + (size_t)(q0 + r) * 64 + ch * 8;
      uint32_t dst = sb + comp * AREA_B + r * AP_B + ch * 16;
      CPASYNC16(dst, src);
    }
    asm volatile("cp.async.commit_group;" ::: "memory");
  }
  stage_kv(0, 0);
  asm volatile("cp.async.wait_group 1;" ::: "memory");  // Q ready
  __syncthreads();

  uint32_t qh[4][4], ql[4][4];
#pragma unroll
  for (int ks = 0; ks < 4; ks++) {
    uint32_t ro = (uint32_t)((w * 16 + (lane & 7) + ((lane >> 3) & 1) * 8) * AP_B
                           + (ks * 16 + ((lane >> 4) & 1) * 8) * 2);
    LDSM4(qh[ks], sb + ro);
    LDSM4(ql[ks], sb + AREA_B + ro);
  }

  float m0 = -CUDART_INF_F, m1 = -CUDART_INF_F, l0 = 0.f, l1 = 0.f;
  float o[8][4];
#pragma unroll
  for (int t = 0; t < 8; t++)
#pragma unroll
    for (int j = 0; j < 4; j++) o[t][j] = 0.f;

  for (int kt = 0; kt < SEQ/128; kt++) {
    if (kt + 1 < SEQ/128) {
      stage_kv(kt + 1, (kt + 1) & 1);
      asm volatile("cp.async.wait_group 1;" ::: "memory");
    } else {
      asm volatile("cp.async.wait_group 0;" ::: "memory");
    }
    __syncthreads();
    const uint32_t kb = sb + (2 + 4 * (kt & 1)) * AREA_B;

    // ---- S = Q @ K^T (3 terms) ----
    float s[16][4];
#pragma unroll
    for (int nt = 0; nt < 16; nt++)
#pragma unroll
      for (int j = 0; j < 4; j++) s[nt][j] = 0.f;
#pragma unroll
    for (int ks = 0; ks < 4; ks++) {
#pragma unroll
      for (int jj = 0; jj < 8; jj++) {
        uint32_t ro = (uint32_t)((jj * 16 + (lane & 7) + ((lane >> 4) & 1) * 8) * AP_B
                               + (ks * 16 + ((lane >> 3) & 1) * 8) * 2);
        uint32_t bh4[4], bl4[4];
        LDSM4(bh4, kb + ro);
        LDSM4(bl4, kb + AREA_B + ro);
        MMA16816(s[2*jj],   qh[ks], bh4);
        MMA16816(s[2*jj],   qh[ks], bl4);
        MMA16816(s[2*jj],   ql[ks], bh4);
        MMA16816(s[2*jj+1], qh[ks], bh4 + 2);
        MMA16816(s[2*jj+1], qh[ks], bl4 + 2);
        MMA16816(s[2*jj+1], ql[ks], bh4 + 2);
      }
    }

    // ---- online softmax ----
    float mx0 = s[0][0], mx1 = s[0][2];
#pragma unroll
    for (int nt = 0; nt < 16; nt++) {
      mx0 = fmaxf(mx0, fmaxf(s[nt][0], s[nt][1]));
      mx1 = fmaxf(mx1, fmaxf(s[nt][2], s[nt][3]));
    }
    mx0 = fmaxf(mx0, __shfl_xor_sync(0xffffffffu, mx0, 1));
    mx0 = fmaxf(mx0, __shfl_xor_sync(0xffffffffu, mx0, 2));
    mx1 = fmaxf(mx1, __shfl_xor_sync(0xffffffffu, mx1, 1));
    mx1 = fmaxf(mx1, __shfl_xor_sync(0xffffffffu, mx1, 2));
    float mn0 = fmaxf(m0, mx0), mn1 = fmaxf(m1, mx1);
    float a0 = __expf(m0 - mn0), a1 = __expf(m1 - mn1);
    float rs0 = 0.f, rs1 = 0.f;
#pragma unroll
    for (int nt = 0; nt < 16; nt++) {
      s[nt][0] = __expf(s[nt][0] - mn0); rs0 += s[nt][0];
      s[nt][1] = __expf(s[nt][1] - mn0); rs0 += s[nt][1];
      s[nt][2] = __expf(s[nt][2] - mn1); rs1 += s[nt][2];
      s[nt][3] = __expf(s[nt][3] - mn1); rs1 += s[nt][3];
    }
    rs0 += __shfl_xor_sync(0xffffffffu, rs0, 1);
    rs0 += __shfl_xor_sync(0xffffffffu, rs0, 2);
    rs1 += __shfl_xor_sync(0xffffffffu, rs1, 1);
    rs1 += __shfl_xor_sync(0xffffffffu, rs1, 2);
    l0 = l0 * a0 + rs0; l1 = l1 * a1 + rs1;
    m0 = mn0; m1 = mn1;
#pragma unroll
    for (int t = 0; t < 8; t++) {
      o[t][0] *= a0; o[t][1] *= a0; o[t][2] *= a1; o[t][3] *= a1;
    }

    // ---- O += P @ V (3 terms) ----
#pragma unroll
    for (int J = 0; J < 8; J++) {
      uint32_t pah[4], pal[4];
      pah[0] = packbf2(s[2*J][0],   s[2*J][1]);
      pah[1] = packbf2(s[2*J][2],   s[2*J][3]);
      pah[2] = packbf2(s[2*J+1][0], s[2*J+1][1]);
      pah[3] = packbf2(s[2*J+1][2], s[2*J+1][3]);
      pal[0] = packresid(pah[0], s[2*J][0],   s[2*J][1]);
      pal[1] = packresid(pah[1], s[2*J][2],   s[2*J][3]);
      pal[2] = packresid(pah[2], s[2*J+1][0], s[2*J+1][1]);
      pal[3] = packresid(pah[3], s[2*J+1][2], s[2*J+1][3]);
#pragma unroll
      for (int tt = 0; tt < 4; tt++) {
        uint32_t ro = (uint32_t)((J * 16 + (lane & 7) + ((lane >> 3) & 1) * 8) * AP_B
                               + (tt * 16 + ((lane >> 4) & 1) * 8) * 2);
        uint32_t vh4[4], vl4[4];
        LDSM4T(vh4, kb + 2 * AREA_B + ro);
        LDSM4T(vl4, kb + 3 * AREA_B + ro);
        MMA16816(o[2*tt],   pah, vh4);
        MMA16816(o[2*tt],   pah, vl4);
        MMA16816(o[2*tt],   pal, vh4);
        MMA16816(o[2*tt+1], pah, vh4 + 2);
        MMA16816(o[2*tt+1], pah, vl4 + 2);
        MMA16816(o[2*tt+1], pal, vh4 + 2);
      }
    }
    __syncthreads();
  }

  // ---- epilogue ----
  const float i0 = 1.f / l0, i1 = 1.f / l1;
  const int b = bh >> 4, h = bh & 15;
  const int r0 = q0 + w * 16 + g, r1 = r0 + 8;
  const size_t ro0 = (size_t)(b * SEQ + r0) * CDIM + h * 64;
  const size_t ro1 = (size_t)(b * SEQ + r1) * CDIM + h * 64;
#pragma unroll
  for (int t = 0; t < 8; t++) {
    int col = t * 8 + tig * 2;
    float f0 = o[t][0] * i0, f1 = o[t][1] * i0;
    float f2 = o[t][2] * i1, f3 = o[t][3] * i1;
    uint32_t h0 = packbf2(f0, f1), h1 = packbf2(f2, f3);
    *(uint32_t*)&g_Ahi[ro0 + col] = h0;
    *(uint32_t*)&g_Alo[ro0 + col] = packresid(h0, f0, f1);
    *(uint32_t*)&g_Ahi[ro1 + col] = h1;
    *(uint32_t*)&g_Alo[ro1 + col] = packresid(h1, f2, f3);
  }
}

// ---------------- launch ----------------
extern "C" void kernel_launch(void* const* d_in, const int* in_sizes, int n_in,
                              void* d_out, int out_size) {
  const float* x    = (const float*)d_in[0];
  const float* Wqkv = (const float*)d_in[1];
  const float* Wout = (const float*)d_in[2];
  float* out = (float*)d_out;

  float *qkv = nullptr;
  __nv_bfloat16 *Ahi=nullptr,*Alo=nullptr,*Bhi=nullptr,*Blo=nullptr;
  cudaGetSymbolAddress((void**)&qkv, g_qkv);
  cudaGetSymbolAddress((void**)&Ahi, g_Ahi);
  cudaGetSymbolAddress((void**)&Alo, g_Alo);
  cudaGetSymbolAddress((void**)&Bhi, g_Bhi);
  cudaGetSymbolAddress((void**)&Blo, g_Blo);

  cudaFuncSetAttribute(gemm_bf16x3,
                       cudaFuncAttributeMaxDynamicSharedMemorySize, GSM_TOTAL);
  cudaFuncSetAttribute(flash_attn_tc,
                       cudaFuncAttributeMaxDynamicSharedMemorySize, ATT2_SMEM);

  rope_cache_kernel<<<(SEQ*HDIM + 255)/256, 256>>>();
  conv_split_kernel<<<(MROWS*CDIM/4 + 255)/256, 256>>>(x, Ahi, Alo, MROWS*CDIM);
  conv_split_kernel<<<(3*CDIM*CDIM/4 + 255)/256, 256>>>(Wqkv, Bhi, Blo, 3*CDIM*CDIM);
  gemm_bf16x3<<<dim3(3*CDIM/128, MROWS/128), 256, GSM_TOTAL>>>(Ahi, Alo, Bhi, Blo, qkv,
                                                               MROWS, 3*CDIM, CDIM);
  rope_apply_kernel<<<(MROWS*1536 + 255)/256, 256>>>();
  flash_attn_tc<<<dim3(SEQ/128, BHN), 256, ATT2_SMEM>>>();
  conv_split_kernel<<<(CDIM*CDIM/4 + 255)/256, 256>>>(Wout, Bhi, Blo, CDIM*CDIM);
  gemm_bf16x3<<<dim3(CDIM/128, MROWS/128), 256, GSM_TOTAL>>>(Ahi, Alo, Bhi, Blo, out,
                                                             MROWS, CDIM, CDIM);
}